// round 1
// baseline (speedup 1.0000x reference)
#include <cuda_runtime.h>

#define N_NODES 50000
#define N_EDGES 1600000
#define NATT    64
#define NHEAD   4

// Output layout (flattened tuple, C-order):
//   attention: [E, NHEAD]        at offset 0
//   v:         [N, 16, NHEAD]    at offset E*NHEAD
//   prods:     [E, NHEAD]        at offset E*NHEAD + N*NATT
#define ATT_OFF   0
#define V_OFF     (N_EDGES * NHEAD)
#define PRODS_OFF (N_EDGES * NHEAD + N_NODES * NATT)

// Scratch (allocation-free per harness rules)
__device__ float g_Q[N_NODES * NATT];       // prescaled by 1/sqrt(d_k)
__device__ float g_K[N_NODES * NATT];
__device__ float g_denom[N_NODES * NHEAD];

// ---------------------------------------------------------------------------
// K1: fused Q/K/V projection + bias. One 64-thread group per node.
//     Also zeroes g_denom and writes V (permuted) straight into d_out.
// ---------------------------------------------------------------------------
__global__ __launch_bounds__(256) void proj_kernel(
    const float* __restrict__ x,
    const float* __restrict__ Wq, const float* __restrict__ bq,
    const float* __restrict__ Wk, const float* __restrict__ bk,
    const float* __restrict__ Wv, const float* __restrict__ bv,
    float* __restrict__ out)
{
    __shared__ float xs[4][NATT];

    const int lane = threadIdx.x & 63;
    const int sub  = threadIdx.x >> 6;          // 0..3
    const int node = blockIdx.x * 4 + sub;

    // zero the denom scratch (grid covers it: 12500 blocks * 256 = 3.2M threads)
    const int gt = blockIdx.x * 256 + threadIdx.x;
    if (gt < N_NODES * NHEAD) g_denom[gt] = 0.0f;

    if (node < N_NODES) xs[sub][lane] = x[node * NATT + lane];
    __syncthreads();

    if (node >= N_NODES) return;

    float aq = 0.0f, ak = 0.0f, av = 0.0f;
#pragma unroll
    for (int k = 0; k < NATT; k++) {
        const float xv = xs[sub][k];
        aq = fmaf(xv, __ldg(&Wq[k * NATT + lane]), aq);
        ak = fmaf(xv, __ldg(&Wk[k * NATT + lane]), ak);
        av = fmaf(xv, __ldg(&Wv[k * NATT + lane]), av);
    }
    // prescale Q by 1/sqrt(16) = 0.25 so the edge pass writes prods directly
    g_Q[node * NATT + lane] = (aq + __ldg(&bq[lane])) * 0.25f;
    g_K[node * NATT + lane] =  ak + __ldg(&bk[lane]);

    // v output: heads() view -> out[n, d, h] = Vlin[n, h*16 + d]
    const int d = lane & 15, h = lane >> 4;
    out[V_OFF + node * NATT + d * NHEAD + h] = av + __ldg(&bv[lane]);
}

// ---------------------------------------------------------------------------
// K2: per-(edge, head) dot product, prods + exp + segment-sum via atomics.
// ---------------------------------------------------------------------------
__global__ __launch_bounds__(256) void edge_kernel(
    const int* __restrict__ edge,
    float* __restrict__ out)
{
    const int t = blockIdx.x * 256 + threadIdx.x;
    if (t >= N_EDGES * NHEAD) return;

    const int e = t >> 2;
    const int h = t & 3;
    const int s = __ldg(&edge[e]);            // source node (segment id)
    const int v = __ldg(&edge[N_EDGES + e]);  // destination node

    const float4* __restrict__ qp = (const float4*)(g_Q + s * NATT + h * 16);
    const float4* __restrict__ kp = (const float4*)(g_K + v * NATT + h * 16);

    float acc = 0.0f;
#pragma unroll
    for (int i = 0; i < 4; i++) {
        const float4 q = qp[i];
        const float4 k = kp[i];
        acc = fmaf(q.x, k.x, acc);
        acc = fmaf(q.y, k.y, acc);
        acc = fmaf(q.z, k.z, acc);
        acc = fmaf(q.w, k.w, acc);
    }

    out[PRODS_OFF + t] = acc;                 // prods (Q already prescaled)
    const float ex = __expf(acc);             // max-subtraction is a no-op here
    out[ATT_OFF + t] = ex;                    // numerator staged in-place
    atomicAdd(&g_denom[s * NHEAD + h], ex);
}

// ---------------------------------------------------------------------------
// K3: normalize attention by segment sum.
// ---------------------------------------------------------------------------
__global__ __launch_bounds__(256) void norm_kernel(
    const int* __restrict__ edge,
    float* __restrict__ out)
{
    const int t = blockIdx.x * 256 + threadIdx.x;
    if (t >= N_EDGES * NHEAD) return;

    const int e = t >> 2;
    const int h = t & 3;
    const int s = __ldg(&edge[e]);

    out[ATT_OFF + t] = out[ATT_OFF + t] / (g_denom[s * NHEAD + h] + 1e-16f);
}

// ---------------------------------------------------------------------------
extern "C" void kernel_launch(void* const* d_in, const int* in_sizes, int n_in,
                              void* d_out, int out_size)
{
    const float* x    = (const float*)d_in[0];
    const int*   edge = (const int*)  d_in[1];
    const float* Wq   = (const float*)d_in[2];
    const float* bq   = (const float*)d_in[3];
    const float* Wk   = (const float*)d_in[4];
    const float* bk   = (const float*)d_in[5];
    const float* Wv   = (const float*)d_in[6];
    const float* bv   = (const float*)d_in[7];
    float* out = (float*)d_out;

    const int proj_blocks = (N_NODES + 3) / 4;                 // 12500
    const int edge_blocks = (N_EDGES * NHEAD + 255) / 256;     // 25000

    proj_kernel<<<proj_blocks, 256>>>(x, Wq, bq, Wk, bk, Wv, bv, out);
    edge_kernel<<<edge_blocks, 256>>>(edge, out);
    norm_kernel<<<edge_blocks, 256>>>(edge, out);
}

// round 2
// speedup vs baseline: 2.1732x; 2.1732x over previous
#include <cuda_runtime.h>
#include <cuda_fp16.h>

#define N_NODES 50000
#define N_EDGES 1600000
#define NATT    64
#define NHEAD   4

// Output layout (flattened tuple, C-order):
//   attention: [E, NHEAD]        at offset 0
//   v:         [N, 16, NHEAD]    at offset E*NHEAD
//   prods:     [E, NHEAD]        at offset E*NHEAD + N*NATT
#define ATT_OFF   0
#define V_OFF     (N_EDGES * NHEAD)
#define PRODS_OFF (N_EDGES * NHEAD + N_NODES * NATT)

// Scratch (allocation-free per harness rules). Q/K stored fp16 (halves gather BW).
__device__ __half g_Qh[N_NODES * NATT];     // prescaled by 1/sqrt(d_k)
__device__ __half g_Kh[N_NODES * NATT];
__device__ float  g_denom[N_NODES * NHEAD];

// Packed f32x2 FMA (Blackwell FFMA2 — only reachable via PTX).
__device__ __forceinline__ float2 ffma2(float2 a, float2 b, float2 c) {
    unsigned long long ra = *reinterpret_cast<unsigned long long*>(&a);
    unsigned long long rb = *reinterpret_cast<unsigned long long*>(&b);
    unsigned long long rc = *reinterpret_cast<unsigned long long*>(&c);
    unsigned long long rd;
    asm("fma.rn.f32x2 %0, %1, %2, %3;" : "=l"(rd) : "l"(ra), "l"(rb), "l"(rc));
    return *reinterpret_cast<float2*>(&rd);
}

// ---------------------------------------------------------------------------
// K1: fused Q/K/V projection. 256 threads = 4 groups x 64 lanes.
//     Each group register-blocks 8 nodes (4 f32x2 pairs) per output column.
//     W elements are reused 8x from registers; FMAs run on the f32x2 pipe.
// ---------------------------------------------------------------------------
#define NPB 32   // nodes per block

__global__ __launch_bounds__(256) void proj_kernel(
    const float* __restrict__ x,
    const float* __restrict__ Wq, const float* __restrict__ bq,
    const float* __restrict__ Wk, const float* __restrict__ bk,
    const float* __restrict__ Wv, const float* __restrict__ bv,
    float* __restrict__ out)
{
    __shared__ float xs_t[NATT][36];   // [k][node_local], padded; float4-aligned

    const int tid  = threadIdx.x;
    const int base = blockIdx.x * NPB;

    // zero denom scratch (1563 blocks * 256 = 400128 threads >= 200000)
    const int gt = blockIdx.x * 256 + tid;
    if (gt < N_NODES * NHEAD) g_denom[gt] = 0.0f;

    // cooperative transposed load of x[base .. base+31][0..63]
    {
        const int nl = tid >> 3;          // 0..31
        const int k0 = (tid & 7) * 8;     // 0,8,...,56
        const int node = base + nl;
        if (node < N_NODES) {
            const float4 a = *(const float4*)&x[node * NATT + k0];
            const float4 b = *(const float4*)&x[node * NATT + k0 + 4];
            xs_t[k0 + 0][nl] = a.x; xs_t[k0 + 1][nl] = a.y;
            xs_t[k0 + 2][nl] = a.z; xs_t[k0 + 3][nl] = a.w;
            xs_t[k0 + 4][nl] = b.x; xs_t[k0 + 5][nl] = b.y;
            xs_t[k0 + 6][nl] = b.z; xs_t[k0 + 7][nl] = b.w;
        }
    }
    __syncthreads();

    const int lane = tid & 63;
    const int g    = tid >> 6;           // 0..3
    const int gn   = g * 8;              // first local node of this group

    float2 aq[4], ak[4], av[4];
#pragma unroll
    for (int j = 0; j < 4; j++) {
        aq[j] = make_float2(0.f, 0.f);
        ak[j] = make_float2(0.f, 0.f);
        av[j] = make_float2(0.f, 0.f);
    }

#pragma unroll
    for (int k = 0; k < NATT; k++) {
        const float wq = __ldg(&Wq[k * NATT + lane]);
        const float wk = __ldg(&Wk[k * NATT + lane]);
        const float wv = __ldg(&Wv[k * NATT + lane]);
        const float2 wq2 = make_float2(wq, wq);
        const float2 wk2 = make_float2(wk, wk);
        const float2 wv2 = make_float2(wv, wv);

        const float4 xa = *(const float4*)&xs_t[k][gn];
        const float4 xb = *(const float4*)&xs_t[k][gn + 4];
        const float2 xp[4] = { make_float2(xa.x, xa.y), make_float2(xa.z, xa.w),
                               make_float2(xb.x, xb.y), make_float2(xb.z, xb.w) };
#pragma unroll
        for (int j = 0; j < 4; j++) {
            aq[j] = ffma2(xp[j], wq2, aq[j]);
            ak[j] = ffma2(xp[j], wk2, ak[j]);
            av[j] = ffma2(xp[j], wv2, av[j]);
        }
    }

    const float bqv = __ldg(&bq[lane]);
    const float bkv = __ldg(&bk[lane]);
    const float bvv = __ldg(&bv[lane]);
    const int d = lane & 15, h = lane >> 4;

#pragma unroll
    for (int j = 0; j < 4; j++) {
        const int n0 = base + gn + 2 * j;
        const float qv0 = (aq[j].x + bqv) * 0.25f;  // prescale by 1/sqrt(16)
        const float qv1 = (aq[j].y + bqv) * 0.25f;
        const float kv0 =  ak[j].x + bkv;
        const float kv1 =  ak[j].y + bkv;
        if (n0 < N_NODES) {
            g_Qh[n0 * NATT + lane] = __float2half(qv0);
            g_Kh[n0 * NATT + lane] = __float2half(kv0);
            out[V_OFF + n0 * NATT + d * NHEAD + h] = av[j].x + bvv;
        }
        if (n0 + 1 < N_NODES) {
            g_Qh[(n0 + 1) * NATT + lane] = __float2half(qv1);
            g_Kh[(n0 + 1) * NATT + lane] = __float2half(kv1);
            out[V_OFF + (n0 + 1) * NATT + d * NHEAD + h] = av[j].y + bvv;
        }
    }
}

// ---------------------------------------------------------------------------
// K2: per-(edge, head) dot product on fp16 Q/K (fp32 accumulate),
//     prods + exp + segment-sum via atomics.
// ---------------------------------------------------------------------------
__global__ __launch_bounds__(256) void edge_kernel(
    const int* __restrict__ edge,
    float* __restrict__ out)
{
    const int t = blockIdx.x * 256 + threadIdx.x;
    if (t >= N_EDGES * NHEAD) return;

    const int e = t >> 2;
    const int h = t & 3;
    const int s = __ldg(&edge[e]);            // source node (segment id)
    const int v = __ldg(&edge[N_EDGES + e]);  // destination node

    // 16 halves per head = 32B = 2 x float4
    const float4* __restrict__ qp = (const float4*)(g_Qh + s * NATT + h * 16);
    const float4* __restrict__ kp = (const float4*)(g_Kh + v * NATT + h * 16);

    float acc = 0.0f;
#pragma unroll
    for (int i = 0; i < 2; i++) {
        float4 qv = qp[i];
        float4 kv = kp[i];
        const __half2* qh = (const __half2*)&qv;
        const __half2* kh = (const __half2*)&kv;
#pragma unroll
        for (int j = 0; j < 4; j++) {
            const float2 qf = __half22float2(qh[j]);
            const float2 kf = __half22float2(kh[j]);
            acc = fmaf(qf.x, kf.x, acc);
            acc = fmaf(qf.y, kf.y, acc);
        }
    }

    out[PRODS_OFF + t] = acc;                 // prods (Q already prescaled)
    const float ex = __expf(acc);             // max-subtraction is a no-op here
    out[ATT_OFF + t] = ex;                    // numerator staged in-place
    atomicAdd(&g_denom[s * NHEAD + h], ex);
}

// ---------------------------------------------------------------------------
// K3: normalize attention by segment sum.
// ---------------------------------------------------------------------------
__global__ __launch_bounds__(256) void norm_kernel(
    const int* __restrict__ edge,
    float* __restrict__ out)
{
    const int t = blockIdx.x * 256 + threadIdx.x;
    if (t >= N_EDGES * NHEAD) return;

    const int e = t >> 2;
    const int h = t & 3;
    const int s = __ldg(&edge[e]);

    out[ATT_OFF + t] = __fdividef(out[ATT_OFF + t], g_denom[s * NHEAD + h] + 1e-16f);
}

// ---------------------------------------------------------------------------
extern "C" void kernel_launch(void* const* d_in, const int* in_sizes, int n_in,
                              void* d_out, int out_size)
{
    const float* x    = (const float*)d_in[0];
    const int*   edge = (const int*)  d_in[1];
    const float* Wq   = (const float*)d_in[2];
    const float* bq   = (const float*)d_in[3];
    const float* Wk   = (const float*)d_in[4];
    const float* bk   = (const float*)d_in[5];
    const float* Wv   = (const float*)d_in[6];
    const float* bv   = (const float*)d_in[7];
    float* out = (float*)d_out;

    const int proj_blocks = (N_NODES + NPB - 1) / NPB;         // 1563
    const int edge_blocks = (N_EDGES * NHEAD + 255) / 256;     // 25000

    proj_kernel<<<proj_blocks, 256>>>(x, Wq, bq, Wk, bk, Wv, bv, out);
    edge_kernel<<<edge_blocks, 256>>>(edge, out);
    norm_kernel<<<edge_blocks, 256>>>(edge, out);
}